// round 6
// baseline (speedup 1.0000x reference)
#include <cuda_runtime.h>

#define NUM_CLASSES 1000
#define FEAT_DIM 512
#define BATCH 65536
#define NSLAB 32
#define HIST_THREADS 256
#define THREADS 256
#define WARPS_PER_BLOCK (THREADS / 32)      // 8
#define NBLOCKS (BATCH / WARPS_PER_BLOCK)   // 8192

// Per-block partial histograms, transposed: g_part[class][slab].
// Fully overwritten by K1 every call -> no reset, no atomics, deterministic.
__device__ int g_part[NUM_CLASSES * NSLAB];

// K1: 32 blocks; each builds a private smem histogram of its 2048 labels and
// stores it into its slab column with plain STGs. Block 0 zeroes out[0].
__global__ void __launch_bounds__(HIST_THREADS) cl_hist_kernel(
    const long long* __restrict__ labels,
    float* __restrict__ out)
{
    __shared__ int h[NUM_CLASSES];
    for (int c = threadIdx.x; c < NUM_CLASSES; c += HIST_THREADS) h[c] = 0;
    if (blockIdx.x == 0 && threadIdx.x == 0) out[0] = 0.0f;
    __syncthreads();

    const longlong2* lab2 =
        reinterpret_cast<const longlong2*>(labels + (size_t)blockIdx.x * (BATCH / NSLAB));
#pragma unroll
    for (int i = 0; i < 4; i++) {
        longlong2 v = lab2[threadIdx.x * 4 + i];
        atomicAdd(&h[(int)v.x], 1);
        atomicAdd(&h[(int)v.y], 1);
    }
    __syncthreads();

    int b = blockIdx.x;
    for (int c = threadIdx.x; c < NUM_CLASSES; c += HIST_THREADS)
        g_part[c * NSLAB + b] = h[c];
}

// K2: one warp per row; 64-reg budget so all 4 feature loads are issued
// back-to-back (MLP_p1=4 DRAM loads/lane), then 4 cached center loads.
// Count from slab partials (one L1-hot 128B line per warp). One un-fenced
// atomicAdd(out) per block. No scratch mutation -> replay-safe.
__global__ void __launch_bounds__(THREADS, 4) cl_main_kernel(
    const float* __restrict__ features,
    const float* __restrict__ centers,
    const long long* __restrict__ labels,
    float* __restrict__ out)
{
    __shared__ float red[WARPS_PER_BLOCK];

    int warp = threadIdx.x >> 5;
    int lane = threadIdx.x & 31;
    int row = blockIdx.x * WARPS_PER_BLOCK + warp;

    int lab = (int)labels[row];  // warp-uniform broadcast load

    const float4* frow = reinterpret_cast<const float4*>(features + (size_t)row * FEAT_DIM);
    const float4* crow = reinterpret_cast<const float4*>(centers + (size_t)lab * FEAT_DIM);

    // Front-batch: 4 streaming DRAM loads in flight, then count partial,
    // then 4 cached center loads.
    float4 fa0 = __ldcs(frow + lane);
    float4 fa1 = __ldcs(frow + lane + 32);
    float4 fa2 = __ldcs(frow + lane + 64);
    float4 fa3 = __ldcs(frow + lane + 96);
    int cnt = __ldg(&g_part[lab * NSLAB + lane]);
    float4 cb0 = __ldg(crow + lane);
    float4 cb1 = __ldg(crow + lane + 32);
    float4 cb2 = __ldg(crow + lane + 64);
    float4 cb3 = __ldg(crow + lane + 96);

    float a0, a1, a2, a3;
    {
        float dx = fa0.x - cb0.x, dy = fa0.y - cb0.y, dz = fa0.z - cb0.z, dw = fa0.w - cb0.w;
        a0 = dx * dx + dy * dy + dz * dz + dw * dw;
    }
    {
        float dx = fa1.x - cb1.x, dy = fa1.y - cb1.y, dz = fa1.z - cb1.z, dw = fa1.w - cb1.w;
        a1 = dx * dx + dy * dy + dz * dz + dw * dw;
    }
    {
        float dx = fa2.x - cb2.x, dy = fa2.y - cb2.y, dz = fa2.z - cb2.z, dw = fa2.w - cb2.w;
        a2 = dx * dx + dy * dy + dz * dz + dw * dw;
    }
    {
        float dx = fa3.x - cb3.x, dy = fa3.y - cb3.y, dz = fa3.z - cb3.z, dw = fa3.w - cb3.w;
        a3 = dx * dx + dy * dy + dz * dz + dw * dw;
    }
    float acc = (a0 + a1) + (a2 + a3);

#pragma unroll
    for (int o = 16; o; o >>= 1) {
        acc += __shfl_xor_sync(0xffffffffu, acc, o);
        cnt += __shfl_xor_sync(0xffffffffu, cnt, o);
    }

    if (lane == 0) {
        float w = __fdividef(1.0f, (float)cnt * (float)FEAT_DIM) * (1.0f / (float)BATCH);
        red[warp] = acc * w;
    }
    __syncthreads();

    if (warp == 0) {
        float v = (lane < WARPS_PER_BLOCK) ? red[lane] : 0.0f;
#pragma unroll
        for (int o = 4; o; o >>= 1)
            v += __shfl_xor_sync(0xffffffffu, v, o);
        if (lane == 0)
            atomicAdd(out, v);
    }
}

extern "C" void kernel_launch(void* const* d_in, const int* in_sizes, int n_in,
                              void* d_out, int out_size) {
    const float* features = (const float*)d_in[0];
    const float* centers = (const float*)d_in[1];
    const long long* labels = (const long long*)d_in[2];
    float* out = (float*)d_out;

    cl_hist_kernel<<<NSLAB, HIST_THREADS>>>(labels, out);
    cl_main_kernel<<<NBLOCKS, THREADS>>>(features, centers, labels, out);
}

// round 7
// speedup vs baseline: 1.0359x; 1.0359x over previous
#include <cuda_runtime.h>

#define NUM_CLASSES 1000
#define FEAT_DIM 512
#define BATCH 65536
#define NSLAB 32
#define HIST_THREADS 256
#define THREADS 512
#define WARPS_PER_BLOCK (THREADS / 32)      // 16
#define NBLOCKS (BATCH / WARPS_PER_BLOCK)   // 4096

// Per-block partial histograms, transposed: g_part[class][slab].
// Fully overwritten by K1 every call -> no reset, no atomics, deterministic.
__device__ int g_part[NUM_CLASSES * NSLAB];

// K1: 32 blocks; each builds a private smem histogram of its 2048 labels and
// stores it into its slab column with plain STGs. Block 0 zeroes out[0].
__global__ void __launch_bounds__(HIST_THREADS) cl_hist_kernel(
    const long long* __restrict__ labels,
    float* __restrict__ out)
{
    __shared__ int h[NUM_CLASSES];
    for (int c = threadIdx.x; c < NUM_CLASSES; c += HIST_THREADS) h[c] = 0;
    if (blockIdx.x == 0 && threadIdx.x == 0) out[0] = 0.0f;
    __syncthreads();

    const longlong2* lab2 =
        reinterpret_cast<const longlong2*>(labels + (size_t)blockIdx.x * (BATCH / NSLAB));
#pragma unroll
    for (int i = 0; i < 4; i++) {
        longlong2 v = lab2[threadIdx.x * 4 + i];
        atomicAdd(&h[(int)v.x], 1);
        atomicAdd(&h[(int)v.y], 1);
    }
    __syncthreads();

    int b = blockIdx.x;
    for (int c = threadIdx.x; c < NUM_CLASSES; c += HIST_THREADS)
        g_part[c * NSLAB + b] = h[c];
}

// K2: one warp per row. 2-deep load batching at ~42 regs / 48 warps per SM:
// two streaming feature float4s + two cached center float4s in flight per
// step. Count from slab partials (one L1-hot 128B line per warp). One
// un-fenced atomicAdd(out) per block. No scratch mutation -> replay-safe.
__global__ void __launch_bounds__(THREADS, 3) cl_main_kernel(
    const float* __restrict__ features,
    const float* __restrict__ centers,
    const long long* __restrict__ labels,
    float* __restrict__ out)
{
    __shared__ float red[WARPS_PER_BLOCK];

    int warp = threadIdx.x >> 5;
    int lane = threadIdx.x & 31;
    int row = blockIdx.x * WARPS_PER_BLOCK + warp;

    int lab = (int)labels[row];  // warp-uniform broadcast load

    const float4* frow = reinterpret_cast<const float4*>(features + (size_t)row * FEAT_DIM);
    const float4* crow = reinterpret_cast<const float4*>(centers + (size_t)lab * FEAT_DIM);

    int cnt = __ldg(&g_part[lab * NSLAB + lane]);

    // Step 1: batch two streaming + two cached loads.
    float4 fa0 = __ldcs(frow + lane);
    float4 fa1 = __ldcs(frow + lane + 32);
    float4 cb0 = __ldg(crow + lane);
    float4 cb1 = __ldg(crow + lane + 32);

    float a0, a1;
    {
        float dx = fa0.x - cb0.x, dy = fa0.y - cb0.y, dz = fa0.z - cb0.z, dw = fa0.w - cb0.w;
        a0 = dx * dx + dy * dy + dz * dz + dw * dw;
    }

    // Step 2 loads issued while step-1 compute drains.
    float4 fa2 = __ldcs(frow + lane + 64);
    float4 fa3 = __ldcs(frow + lane + 96);
    float4 cb2 = __ldg(crow + lane + 64);
    float4 cb3 = __ldg(crow + lane + 96);

    {
        float dx = fa1.x - cb1.x, dy = fa1.y - cb1.y, dz = fa1.z - cb1.z, dw = fa1.w - cb1.w;
        a1 = dx * dx + dy * dy + dz * dz + dw * dw;
    }
    {
        float dx = fa2.x - cb2.x, dy = fa2.y - cb2.y, dz = fa2.z - cb2.z, dw = fa2.w - cb2.w;
        a0 += dx * dx + dy * dy + dz * dz + dw * dw;
    }
    {
        float dx = fa3.x - cb3.x, dy = fa3.y - cb3.y, dz = fa3.z - cb3.z, dw = fa3.w - cb3.w;
        a1 += dx * dx + dy * dy + dz * dz + dw * dw;
    }
    float acc = a0 + a1;

#pragma unroll
    for (int o = 16; o; o >>= 1) {
        acc += __shfl_xor_sync(0xffffffffu, acc, o);
        cnt += __shfl_xor_sync(0xffffffffu, cnt, o);
    }

    if (lane == 0) {
        float w = __fdividef(1.0f, (float)cnt * (float)FEAT_DIM) * (1.0f / (float)BATCH);
        red[warp] = acc * w;
    }
    __syncthreads();

    if (warp == 0) {
        float v = (lane < WARPS_PER_BLOCK) ? red[lane] : 0.0f;
#pragma unroll
        for (int o = 8; o; o >>= 1)
            v += __shfl_xor_sync(0xffffffffu, v, o);
        if (lane == 0)
            atomicAdd(out, v);
    }
}

extern "C" void kernel_launch(void* const* d_in, const int* in_sizes, int n_in,
                              void* d_out, int out_size) {
    const float* features = (const float*)d_in[0];
    const float* centers = (const float*)d_in[1];
    const long long* labels = (const long long*)d_in[2];
    float* out = (float*)d_out;

    cl_hist_kernel<<<NSLAB, HIST_THREADS>>>(labels, out);
    cl_main_kernel<<<NBLOCKS, THREADS>>>(features, centers, labels, out);
}